// round 6
// baseline (speedup 1.0000x reference)
#include <cuda_runtime.h>
#include <math.h>
#include <stdint.h>

// ===========================================================================
// StreamingSSMCell (B=8192, D=1024, DCONV=4) — fma.rn.f32x2 GEMM v2
//   Accumulators packed over N: B fragments are native u64 loads (no packs),
//   B smem reads are warp-broadcast (conflict-free), A reads stride-8B.
//   d_out layout: [ out (B*D) | h_new (B*D) | new_buf (B*D*4) ]
// ===========================================================================

#define D_MODEL 1024
#define TWO_D   2048
#define BATCH   8192

__device__ float g_xz[(size_t)BATCH * TWO_D];
__device__ float g_g [(size_t)BATCH * D_MODEL];

// ------------------------------ GEMM config --------------------------------
#define BM 128
#define BN 128
#define BK 16
#define ASTR 132                 // padded words per k-row
#define NTHREADS 256

typedef unsigned long long u64;

#define FMA2(c, a, b) \
    asm("fma.rn.f32x2 %0, %1, %2, %0;" : "+l"(c) : "l"(a), "l"(b))

#define PACK2F(d, x) \
    asm("mov.b64 %0, {%1, %1};" : "=l"(d) : "f"(x))

#define UNPACK2(lo, hi, s) \
    asm("mov.b64 {%0, %1}, %2;" : "=f"(lo), "=f"(hi) : "l"(s))

// ------------------------- packed-fp32 GEMM v2 -----------------------------
// C[m,n] = sum_k A[m,k]*Bm[n,k] + bias[n]; A [M,K] lda, Bm [N,K] ldb (K-major)
// grid = (N/128, M/128), 256 threads (8 warps = 2 m-halves x 4 n-slabs).
// Thread: rows (wm*64 + lane*2, +1), cols [wn*32, wn*32+32); acc packed (n,n+1).
__global__ __launch_bounds__(NTHREADS, 2)
void gemm_f32x2(const float* __restrict__ A, int lda,
                const float* __restrict__ Bm, int ldb,
                const float* __restrict__ bias,
                float* __restrict__ C, int ldc, int K)
{
    __shared__ float As[2][BK][ASTR];
    __shared__ float Bs[2][BK][ASTR];

    const int tid  = threadIdx.x;
    const int lane = tid & 31;
    const int wid  = tid >> 5;
    const int wm = wid >> 2;            // 0..1
    const int wn = wid & 3;             // 0..3
    const int m0 = blockIdx.y * BM;
    const int n0 = blockIdx.x * BN;

    // global load mapping: r0 = tid>>2 (0..63), kc = tid&3 (float4 chunk)
    const int r0 = tid >> 2;
    const int kc = tid & 3;
    const float* gA0 = A  + (size_t)(m0 + r0)      * lda + kc * 4;
    const float* gA1 = A  + (size_t)(m0 + r0 + 64) * lda + kc * 4;
    const float* gB0 = Bm + (size_t)(n0 + r0)      * ldb + kc * 4;
    const float* gB1 = Bm + (size_t)(n0 + r0 + 64) * ldb + kc * 4;

    u64 acc[2][16];
    #pragma unroll
    for (int r = 0; r < 2; r++)
        #pragma unroll
        for (int c = 0; c < 16; c++) acc[r][c] = 0ULL;

    const int T = K / BK;

    float4 ra0, ra1, rb0, rb1;

    // prologue
    ra0 = *(const float4*)(gA0);
    ra1 = *(const float4*)(gA1);
    rb0 = *(const float4*)(gB0);
    rb1 = *(const float4*)(gB1);
    #pragma unroll
    for (int j = 0; j < 4; j++) {
        As[0][kc * 4 + j][r0]      = ((const float*)&ra0)[j];
        As[0][kc * 4 + j][r0 + 64] = ((const float*)&ra1)[j];
        Bs[0][kc * 4 + j][r0]      = ((const float*)&rb0)[j];
        Bs[0][kc * 4 + j][r0 + 64] = ((const float*)&rb1)[j];
    }
    __syncthreads();

    for (int t = 0; t < T; t++) {
        const int buf = t & 1;

        if (t + 1 < T) {
            const size_t off = (size_t)(t + 1) * BK;
            ra0 = *(const float4*)(gA0 + off);
            ra1 = *(const float4*)(gA1 + off);
            rb0 = *(const float4*)(gB0 + off);
            rb1 = *(const float4*)(gB1 + off);
        }

        #pragma unroll
        for (int k = 0; k < BK; k++) {
            const float2 av = *(const float2*)&As[buf][k][wm * 64 + lane * 2];
            u64 a0, a1;
            PACK2F(a0, av.x);
            PACK2F(a1, av.y);

            const ulonglong2* bp =
                (const ulonglong2*)&Bs[buf][k][wn * 32];   // 16B-aligned
            #pragma unroll
            for (int q = 0; q < 8; q++) {
                const ulonglong2 bq = bp[q];               // broadcast LDS.128
                FMA2(acc[0][2 * q],     a0, bq.x);
                FMA2(acc[1][2 * q],     a1, bq.x);
                FMA2(acc[0][2 * q + 1], a0, bq.y);
                FMA2(acc[1][2 * q + 1], a1, bq.y);
            }
        }

        if (t + 1 < T) {
            const int nb = (t + 1) & 1;
            #pragma unroll
            for (int j = 0; j < 4; j++) {
                As[nb][kc * 4 + j][r0]      = ((const float*)&ra0)[j];
                As[nb][kc * 4 + j][r0 + 64] = ((const float*)&ra1)[j];
                Bs[nb][kc * 4 + j][r0]      = ((const float*)&rb0)[j];
                Bs[nb][kc * 4 + j][r0 + 64] = ((const float*)&rb1)[j];
            }
            __syncthreads();
        }
    }

    // epilogue: unpack (cols 2c,2c+1 consecutive), add bias, STG.128
    #pragma unroll
    for (int r = 0; r < 2; r++) {
        const int m = m0 + wm * 64 + lane * 2 + r;
        float* crow = C + (size_t)m * ldc + n0 + wn * 32;
        #pragma unroll
        for (int c = 0; c < 16; c += 2) {
            const float4 bb = *(const float4*)(bias + n0 + wn * 32 + 2 * c);
            float l0, h0, l1, h1;
            UNPACK2(l0, h0, acc[r][c]);
            UNPACK2(l1, h1, acc[r][c + 1]);
            float4 v;
            v.x = l0 + bb.x; v.y = h0 + bb.y; v.z = l1 + bb.z; v.w = h1 + bb.w;
            *(float4*)(crow + 2 * c) = v;
        }
    }
}

// ------------------------ fused elementwise stage ---------------------------
__device__ __forceinline__ float silu_f(float x) { return x / (1.0f + expf(-x)); }

__global__ void fused_elementwise(const float* __restrict__ xz,
                                  const float* __restrict__ h,
                                  const float* __restrict__ conv_buf,
                                  const float* __restrict__ conv_w,
                                  const float* __restrict__ conv_b,
                                  float* __restrict__ out_hnew,
                                  float* __restrict__ out_newbuf,
                                  float* __restrict__ g_out,
                                  int B, int D)
{
    const int idx = blockIdx.x * blockDim.x + threadIdx.x;
    if (idx >= B * D) return;
    const int b = idx / D;
    const int d = idx - b * D;

    const float xi = xz[(size_t)b * 2 * D + d];
    const float z  = xz[(size_t)b * 2 * D + D + d];

    const float4 cb = *(const float4*)(conv_buf + (size_t)idx * 4);
    const float4 cw = *(const float4*)(conv_w + (size_t)d * 4);

    float co = cb.y * cw.x + cb.z * cw.y + cb.w * cw.z + xi * cw.w + conv_b[d];
    co = silu_f(co);

    const float lmin = 2.302585092994046f;   // log(10)
    const float lmax = 7.600902459542082f;   // log(2000)
    const float t = lmin + (float)d * (lmax - lmin) / (float)(D - 1);
    const float dec = expf(-expf(-t));

    const float hn = dec * h[idx] + (1.0f - dec) * co;

    out_hnew[idx] = hn;
    float4 nb; nb.x = cb.y; nb.y = cb.z; nb.z = cb.w; nb.w = xi;
    *(float4*)(out_newbuf + (size_t)idx * 4) = nb;

    g_out[idx] = hn * silu_f(z);
}

// ------------------------------- launch ------------------------------------
extern "C" void kernel_launch(void* const* d_in, const int* in_sizes, int n_in,
                              void* d_out, int out_size)
{
    const float* x        = (const float*)d_in[0];
    const float* h        = (const float*)d_in[1];
    const float* conv_buf = (const float*)d_in[2];
    const float* W_in     = (const float*)d_in[3];
    const float* b_in     = (const float*)d_in[4];
    const float* conv_w   = (const float*)d_in[5];
    const float* conv_b   = (const float*)d_in[6];
    const float* W_out    = (const float*)d_in[7];
    const float* b_out    = (const float*)d_in[8];

    const int D = in_sizes[6];
    const int B = in_sizes[0] / D;
    const int twoD = in_sizes[4];

    float* out      = (float*)d_out;
    float* out_hnew = out + (size_t)B * D;
    float* out_nbuf = out + (size_t)2 * B * D;

    float* xz = g_xz;
    float* gg = g_g;

    // GEMM1: xz = x @ W_in^T + b_in   [B, 2D]
    {
        dim3 grid(twoD / BN, B / BM);
        gemm_f32x2<<<grid, NTHREADS>>>(x, D, W_in, D, b_in, xz, twoD, D);
    }

    // fused elementwise
    {
        const int n = B * D;
        fused_elementwise<<<(n + 255) / 256, 256>>>(
            xz, h, conv_buf, conv_w, conv_b, out_hnew, out_nbuf, gg, B, D);
    }

    // GEMM2: out = g @ W_out^T + b_out  [B, D]
    {
        dim3 grid(D / BN, B / BM);
        gemm_f32x2<<<grid, NTHREADS>>>(gg, D, W_out, D, b_out, out, D, D);
    }
}